// round 8
// baseline (speedup 1.0000x reference)
#include <cuda_runtime.h>

// Problem constants (fixed by reference setup_inputs):
//   x:    [8, 256, 256, 64] f32
//   flow: [8, 252, 252, 25] f32
//   out:  [8, 252, 252, 64] f32, ksize = 5
#define KS 5
#define B_ 8
#define H_ 256
#define W_ 256
#define C_ 64
#define HO 252
#define WO 252

// Packed dual-FMA: acc(f32x2) += x(f32x2) * f(f32x2). Only reachable via PTX.
#define FMA2(acc, xv, ff) \
    asm("fma.rn.f32x2 %0, %1, %2, %0;" : "+l"(acc) : "l"(xv), "l"(ff))

// Block: 16 channel-groups (tx) * 16 j-groups (ty) = 256 threads.
// Each thread: 2 output rows (i, i+1) * 4 j pixels * 4 channels.
// Per x row r: walk u = 0..7 (x position j0+u); each loaded xv quad is
// consumed immediately by every (jj, dj) tap with jj+dj == u, then dies.
// Keeps <=4-5 xv quads live -> 64 regs -> 4 blocks/SM.
__global__ __launch_bounds__(256, 4) void dfl_kernel(
    const float* __restrict__ x,
    const float* __restrict__ flow,
    float* __restrict__ out)
{
    // flow for 2 output rows * 64 pixels * 25 taps, pre-duplicated as (f,f)
    // pairs so LDS.64 yields a packed f32x2 multiplier directly.
    __shared__ float2 s_flow[2 * 64 * 25];

    const int tx = threadIdx.x;          // channel group: c = 4*tx
    const int ty = threadIdx.y;          // j group: j0 = j_base + 4*ty
    const int i  = blockIdx.y * 2;       // output rows i, i+1 (i <= 250)
    const int b  = blockIdx.z;
    const int j_base = blockIdx.x * 64;

    // Cooperative flow stage (coalesced reads, duplicated writes).
    {
        const int tid  = ty * 16 + tx;
        const int npix = min(64, WO - j_base);
        const int n    = npix * 25;
        const float* f0 = flow + ((size_t)(b * HO + i) * WO + j_base) * 25;
        const float* f1 = f0 + (size_t)WO * 25;
        for (int idx = tid; idx < n; idx += 256) {
            const float v0 = f0[idx];
            const float v1 = f1[idx];
            s_flow[idx]           = make_float2(v0, v0);
            s_flow[64 * 25 + idx] = make_float2(v1, v1);
        }
    }
    __syncthreads();

    const int j0 = j_base + ty * 4;
    if (j0 >= WO) return;                // only last block's ty=15 group

    const int c = tx * 4;

    ulonglong2 acc[2][4];                // [row][jj], each = 4 packed f32
    #pragma unroll
    for (int o = 0; o < 2; ++o)
        #pragma unroll
        for (int jj = 0; jj < 4; ++jj) { acc[o][jj].x = 0ull; acc[o][jj].y = 0ull; }

    const unsigned long long* fl0 = reinterpret_cast<const unsigned long long*>(
        s_flow + (ty * 4) * 25);                 // row i
    const unsigned long long* fl1 = reinterpret_cast<const unsigned long long*>(
        s_flow + 64 * 25 + (ty * 4) * 25);       // row i+1

    // Single base pointer; row r and position u become immediate offsets.
    const ulonglong2* __restrict__ xbase = reinterpret_cast<const ulonglong2*>(
        x + (((size_t)(b * H_ + i) * W_ + j0) * C_ + c));
    const int ROWQ = W_ * C_ / 4;        // ulonglong2 per x row (4096)

    #pragma unroll
    for (int r = 0; r < 6; ++r) {        // x rows i+r; max i+5 = 255, in-bounds
        #pragma unroll
        for (int u = 0; u < 8; ++u) {    // x position j0+u; max 255, in-bounds
            const ulonglong2 xv = xbase[r * ROWQ + u * (C_ / 4)];
            #pragma unroll
            for (int jj = 0; jj < 4; ++jj) {
                const int dj = u - jj;
                if (dj < 0 || dj >= KS) continue;
                if (r <= 4) {            // out row i, di = r
                    const unsigned long long f = fl0[jj * 25 + r * KS + dj];
                    FMA2(acc[0][jj].x, xv.x, f);
                    FMA2(acc[0][jj].y, xv.y, f);
                }
                if (r >= 1) {            // out row i+1, di = r-1
                    const unsigned long long f = fl1[jj * 25 + (r - 1) * KS + dj];
                    FMA2(acc[1][jj].x, xv.x, f);
                    FMA2(acc[1][jj].y, xv.y, f);
                }
            }
        }
    }

    #pragma unroll
    for (int o = 0; o < 2; ++o) {
        ulonglong2* __restrict__ op = reinterpret_cast<ulonglong2*>(
            out + (((size_t)(b * HO + i + o) * WO + j0) * C_ + c));
        #pragma unroll
        for (int jj = 0; jj < 4; ++jj)
            op[jj * (C_ / 4)] = acc[o][jj];
    }
}

extern "C" void kernel_launch(void* const* d_in, const int* in_sizes, int n_in,
                              void* d_out, int out_size) {
    const float* x    = (const float*)d_in[0];
    const float* flow = (const float*)d_in[1];
    float* out = (float*)d_out;

    dim3 grid(4 /* ceil(63 j-groups / 16) */, HO / 2, B_);
    dim3 block(16, 16);
    dfl_kernel<<<grid, block>>>(x, flow, out);
}